// round 7
// baseline (speedup 1.0000x reference)
#include <cuda_runtime.h>

#define SPECIES 4
#define POP     4096
#define DIM     16
#define NTOT    (SPECIES * POP)      // 16384
#define ISPAN   256                  // i-rows per pairwise block (128 thr x 2)
#define JCHUNK  128
#define JSPLIT  (POP / JCHUNK)       // 32
#define NSTEPS  4

#define LBV (-4.0f)
#define UBV (4.0f)
#define LOG2E 1.44269504088896340736f
#define TWOPI 6.283185307179586f

// ---------------- device scratch ----------------
__device__ float  g_xA[NTOT * DIM];     // original-order positions (post-update)
__device__ float  g_xS[NTOT * DIM];     // sorted-order positions
__device__ float  g_cost[NTOT];         // cost, original order
__device__ int    g_perm[NTOT];         // sorted slot -> original p (within species)
__device__ float2 g_scS[NTOT];          // sorted: (-LOG2E*sq, cost)
__device__ float  g_part[JSPLIT * 17 * NTOT];

// ---------------- f32x2 helpers ----------------
__device__ __forceinline__ unsigned long long pack2(float lo, float hi) {
    unsigned long long r;
    asm("mov.b64 %0, {%1, %2};" : "=l"(r) : "f"(lo), "f"(hi));
    return r;
}
__device__ __forceinline__ void unpack2(unsigned long long v, float& lo, float& hi) {
    asm("mov.b64 {%0, %1}, %2;" : "=f"(lo), "=f"(hi) : "l"(v));
}
#define FMA2(d, a, b, c) \
    asm("fma.rn.f32x2 %0, %1, %2, %3;" : "=l"(d) : "l"(a), "l"(b), "l"(c))
#define MUL2(d, a, b) \
    asm("mul.rn.f32x2 %0, %1, %2;" : "=l"(d) : "l"(a), "l"(b))
#define ADD2(d, a, b) \
    asm("add.rn.f32x2 %0, %1, %2;" : "=l"(d) : "l"(a), "l"(b))

// ---------------- monotone float->u32 encode ----------------
__device__ __forceinline__ unsigned int enc_f(float c) {
    unsigned int cb = __float_as_uint(c);
    return (cb & 0x80000000u) ? ~cb : (cb | 0x80000000u);
}

// ---------------- step-0 cost from raw input ----------------
__global__ void cost_kernel(const float* __restrict__ src) {
    int idx = blockIdx.x * blockDim.x + threadIdx.x;
    if (idx >= NTOT) return;
    const float4* xp = reinterpret_cast<const float4*>(src + (size_t)idx * DIM);
    float cost = 10.0f * (float)DIM;
#pragma unroll
    for (int u = 0; u < 4; ++u) {
        float4 xv = xp[u];
        float xs[4] = {xv.x, xv.y, xv.z, xv.w};
#pragma unroll
        for (int t = 0; t < 4; ++t)
            cost += xs[t] * xs[t] - 10.0f * cosf(TWOPI * xs[t]);
    }
    g_cost[idx] = cost;
}

// ---------------- rank sort: brute-force rank by counting + fused scatter ----------------
// grid: SPECIES * (POP/256) = 64 blocks, 256 threads; thread owns one element.
__global__ __launch_bounds__(256) void ranksort_kernel(const float* __restrict__ src) {
    __shared__ unsigned long long skey[POP];   // 32 KB
    const int s  = blockIdx.x / (POP / 256);
    const int el = (blockIdx.x % (POP / 256)) * 256 + threadIdx.x;  // species-local idx

    // stage all keys for this species (coalesced LDG, conflict-free STS)
    for (int t = threadIdx.x; t < POP; t += 256) {
        unsigned int ec = enc_f(g_cost[s * POP + t]);
        skey[t] = ((unsigned long long)ec << 32) | (unsigned int)t;
    }
    __syncthreads();

    const unsigned long long kme = skey[el];
    const float cme = g_cost[s * POP + el];

    int rank = 0;
    const uint4* k4 = reinterpret_cast<const uint4*>(skey);
#pragma unroll 8
    for (int t = 0; t < POP / 2; ++t) {
        uint4 v = k4[t];   // broadcast read: all threads same address
        unsigned long long k0 = ((unsigned long long)v.y << 32) | v.x;
        unsigned long long k1 = ((unsigned long long)v.w << 32) | v.z;
        rank += (int)(k0 < kme) + (int)(k1 < kme);
    }

    // scatter into sorted-slot order
    int r = s * POP + rank;
    g_perm[r] = el;
    const float4* sp = reinterpret_cast<const float4*>(src + (size_t)(s * POP + el) * DIM);
    float4* dp = reinterpret_cast<float4*>(g_xS + (size_t)r * DIM);
    float sq = 0.0f;
#pragma unroll
    for (int q = 0; q < 4; ++q) {
        float4 xv = sp[q];
        dp[q] = xv;
        sq = fmaf(xv.x, xv.x, sq);
        sq = fmaf(xv.y, xv.y, sq);
        sq = fmaf(xv.z, xv.z, sq);
        sq = fmaf(xv.w, xv.w, sq);
    }
    g_scS[r] = make_float2(-LOG2E * sq, cme);
}

// ---------------- pairwise: 2 i-rows per thread, lower-triangle blocks ----------------
// grid: (POP/ISPAN, JSPLIT, SPECIES), block: 128
__global__ __launch_bounds__(128, 4) void pairwise_kernel() {
    if (blockIdx.y * JCHUNK > blockIdx.x * ISPAN + (ISPAN - 1)) return;

    __shared__ float  s_x[JCHUNK * DIM];   // 8 KB
    __shared__ float2 s_sc[JCHUNK];        // 1 KB

    const int s  = blockIdx.z;
    const int i0 = s * POP + blockIdx.x * ISPAN + threadIdx.x;
    const int i1 = i0 + 128;
    const int j0 = s * POP + blockIdx.y * JCHUNK;

    {
        const float4* src = reinterpret_cast<const float4*>(g_xS + (size_t)j0 * DIM);
        float4* dst = reinterpret_cast<float4*>(s_x);
#pragma unroll
        for (int t = threadIdx.x; t < (JCHUNK * DIM) / 4; t += 128)
            dst[t] = src[t];
        if (threadIdx.x < JCHUNK) s_sc[threadIdx.x] = g_scS[j0 + threadIdx.x];
    }
    __syncthreads();

    unsigned long long xi0[8], xi1[8];
    {
        const ulonglong2* xp0 = reinterpret_cast<const ulonglong2*>(g_xS + (size_t)i0 * DIM);
        const ulonglong2* xp1 = reinterpret_cast<const ulonglong2*>(g_xS + (size_t)i1 * DIM);
#pragma unroll
        for (int q = 0; q < 4; ++q) {
            ulonglong2 v0 = xp0[q];
            ulonglong2 v1 = xp1[q];
            xi0[2 * q] = v0.x; xi0[2 * q + 1] = v0.y;
            xi1[2 * q] = v1.x; xi1[2 * q + 1] = v1.y;
        }
    }
    const float2 sci0 = g_scS[i0];
    const float2 sci1 = g_scS[i1];
    const float ai0 = 1.0f + sci0.x, ci0 = sci0.y;
    const float ai1 = 1.0f + sci1.x, ci1 = sci1.y;

    unsigned long long acc0[8], acc1[8];
    const unsigned long long zero2 = pack2(0.0f, 0.0f);
#pragma unroll
    for (int q = 0; q < 8; ++q) { acc0[q] = zero2; acc1[q] = zero2; }
    float ws0 = 0.0f, ws1 = 0.0f;

#pragma unroll 2
    for (int jj = 0; jj < JCHUNK; ++jj) {
        const ulonglong2* xjv = reinterpret_cast<const ulonglong2*>(s_x + jj * DIM);
        ulonglong2 va = xjv[0];
        ulonglong2 vb = xjv[1];
        ulonglong2 vc = xjv[2];
        ulonglong2 vd = xjv[3];
        float2 scj = s_sc[jj];

        unsigned long long pA, pB, qA, qB;
        MUL2(pA, xi0[0], va.x);  MUL2(pB, xi0[1], va.y);
        MUL2(qA, xi1[0], va.x);  MUL2(qB, xi1[1], va.y);
        FMA2(pA, xi0[2], vb.x, pA);  FMA2(pB, xi0[3], vb.y, pB);
        FMA2(qA, xi1[2], vb.x, qA);  FMA2(qB, xi1[3], vb.y, qB);
        FMA2(pA, xi0[4], vc.x, pA);  FMA2(pB, xi0[5], vc.y, pB);
        FMA2(qA, xi1[4], vc.x, qA);  FMA2(qB, xi1[5], vc.y, qB);
        FMA2(pA, xi0[6], vd.x, pA);  FMA2(pB, xi0[7], vd.y, pB);
        FMA2(qA, xi1[6], vd.x, qA);  FMA2(qB, xi1[7], vd.y, qB);

        unsigned long long sp, sq2;
        ADD2(sp, pA, pB);
        ADD2(sq2, qA, qB);
        float p0, p1, q0, q1;
        unpack2(sp, p0, p1);
        unpack2(sq2, q0, q1);
        float d0 = p0 + p1;
        float d1 = q0 + q1;

        float t0 = fmaf(d0, 2.0f * LOG2E, ai0 + scj.x);
        float t1 = fmaf(d1, 2.0f * LOG2E, ai1 + scj.x);
        float w0, w1;
        asm("ex2.approx.f32 %0, %1;" : "=f"(w0) : "f"(t0));
        asm("ex2.approx.f32 %0, %1;" : "=f"(w1) : "f"(t1));
        w0 = (ci0 > scj.y) ? w0 : 0.0f;
        w1 = (ci1 > scj.y) ? w1 : 0.0f;

        unsigned long long w20 = pack2(w0, w0);
        unsigned long long w21 = pack2(w1, w1);
        FMA2(acc0[0], w20, va.x, acc0[0]);  FMA2(acc1[0], w21, va.x, acc1[0]);
        FMA2(acc0[1], w20, va.y, acc0[1]);  FMA2(acc1[1], w21, va.y, acc1[1]);
        FMA2(acc0[2], w20, vb.x, acc0[2]);  FMA2(acc1[2], w21, vb.x, acc1[2]);
        FMA2(acc0[3], w20, vb.y, acc0[3]);  FMA2(acc1[3], w21, vb.y, acc1[3]);
        FMA2(acc0[4], w20, vc.x, acc0[4]);  FMA2(acc1[4], w21, vc.x, acc1[4]);
        FMA2(acc0[5], w20, vc.y, acc0[5]);  FMA2(acc1[5], w21, vc.y, acc1[5]);
        FMA2(acc0[6], w20, vd.x, acc0[6]);  FMA2(acc1[6], w21, vd.x, acc1[6]);
        FMA2(acc0[7], w20, vd.y, acc0[7]);  FMA2(acc1[7], w21, vd.y, acc1[7]);
        ws0 += w0;
        ws1 += w1;
    }

    float* base = g_part + (size_t)blockIdx.y * 17 * NTOT;
#pragma unroll
    for (int q = 0; q < 8; ++q) {
        float lo, hi;
        unpack2(acc0[q], lo, hi);
        base[(2 * q) * NTOT + i0]     = lo;
        base[(2 * q + 1) * NTOT + i0] = hi;
        unpack2(acc1[q], lo, hi);
        base[(2 * q) * NTOT + i1]     = lo;
        base[(2 * q + 1) * NTOT + i1] = hi;
    }
    base[16 * NTOT + i0] = ws0;
    base[16 * NTOT + i1] = ws1;
}

// ---------------- update: 8 threads per firefly (2 dims each) ----------------
__global__ __launch_bounds__(256) void update_kernel(float* __restrict__ xout,
                                                     const float* __restrict__ noise_step,
                                                     float alpha, int do_mix) {
    int gid = blockIdx.x * 256 + threadIdx.x;   // 8*NTOT threads
    int r = gid >> 3;                            // sorted slot
    int q = gid & 7;                             // dim pair index
    int s  = r / POP;
    int rl = r % POP;
    int bi = rl / ISPAN;
    int nch = ((bi + 1) * ISPAN - 1) / JCHUNK + 1;

    int p = g_perm[r];
    int orig = s * POP + p;
    int ds = (do_mix && p >= POP / 2) ? ((s + 1) & (SPECIES - 1)) : s;
    int didx = ds * POP + p;

    float ws = 0.0f, a0 = 0.0f, a1 = 0.0f;
#pragma unroll 4
    for (int k = 0; k < nch; ++k) {
        const float* pk = g_part + (size_t)k * 17 * NTOT + r;
        ws += pk[(size_t)16 * NTOT];
        a0 += pk[(size_t)(2 * q) * NTOT];
        a1 += pk[(size_t)(2 * q + 1) * NTOT];
    }

    float2 xv = *reinterpret_cast<const float2*>(g_xS + (size_t)r * DIM + 2 * q);
    float2 nz = *reinterpret_cast<const float2*>(noise_step + (size_t)orig * DIM + 2 * q);
    const float scale = alpha * (UBV - LBV);

    float xn0 = xv.x + (a0 - ws * xv.x) + scale * (nz.x - 0.5f);
    float xn1 = xv.y + (a1 - ws * xv.y) + scale * (nz.y - 0.5f);
    xn0 = fminf(fmaxf(xn0, LBV), UBV);
    xn1 = fminf(fmaxf(xn1, LBV), UBV);
    *reinterpret_cast<float2*>(xout + (size_t)didx * DIM + 2 * q) = make_float2(xn0, xn1);

    float cost = (xn0 * xn0 - 10.0f * cosf(TWOPI * xn0))
               + (xn1 * xn1 - 10.0f * cosf(TWOPI * xn1));
#pragma unroll
    for (int m = 1; m <= 4; m <<= 1)
        cost += __shfl_xor_sync(0xffffffffu, cost, m);
    if (q == 0)
        g_cost[didx] = cost + 10.0f * (float)DIM;
}

// ---------------- launch ----------------
extern "C" void kernel_launch(void* const* d_in, const int* in_sizes, int n_in,
                              void* d_out, int out_size) {
    const float* fireflies = (const float*)d_in[0];
    const float* noise     = (const float*)d_in[1];
    float* out = (float*)d_out;

    float* xA;
    cudaGetSymbolAddress((void**)&xA, g_xA);

    dim3 pw_grid(POP / ISPAN, JSPLIT, SPECIES);
    int rs_blocks = SPECIES * (POP / 256);   // 64

    cost_kernel<<<NTOT / 256, 256>>>(fireflies);

    double alpha = 0.1;
    const float* src = fireflies;
    for (int step = 0; step < NSTEPS; ++step) {
        ranksort_kernel<<<rs_blocks, 256>>>(src);
        pairwise_kernel<<<pw_grid, 128>>>();
        float* dst = (step == NSTEPS - 1) ? out : xA;
        const float* nz = noise + (size_t)step * NTOT * DIM;
        int do_mix = (step % 25 == 0) ? 1 : 0;
        update_kernel<<<NTOT * 8 / 256, 256>>>(dst, nz, (float)alpha, do_mix);
        alpha *= 0.995;
        src = xA;
    }
}

// round 8
// speedup vs baseline: 1.1454x; 1.1454x over previous
#include <cuda_runtime.h>

#define SPECIES 4
#define POP     4096
#define DIM     16
#define NTOT    (SPECIES * POP)      // 16384
#define ISPAN   256                  // i-rows per pairwise block (128 thr x 2)
#define JCHUNK  128
#define JSPLIT  (POP / JCHUNK)       // 32
#define NSTEPS  4

#define LBV (-4.0f)
#define UBV (4.0f)
#define LOG2E 1.44269504088896340736f
#define TWOPI 6.283185307179586f

// ---------------- device scratch ----------------
__device__ float  g_xA[NTOT * DIM];     // original-order positions (post-update)
__device__ float  g_xS[NTOT * DIM];     // sorted-order positions
__device__ float  g_cost[NTOT];         // cost, original order
__device__ int    g_perm[NTOT];         // sorted slot -> original p (within species)
__device__ float2 g_scS[NTOT];          // sorted: (-LOG2E*sq, cost)
__device__ float  g_part[JSPLIT * 17 * NTOT];

// ---------------- f32x2 helpers ----------------
__device__ __forceinline__ unsigned long long pack2(float lo, float hi) {
    unsigned long long r;
    asm("mov.b64 %0, {%1, %2};" : "=l"(r) : "f"(lo), "f"(hi));
    return r;
}
__device__ __forceinline__ void unpack2(unsigned long long v, float& lo, float& hi) {
    asm("mov.b64 {%0, %1}, %2;" : "=f"(lo), "=f"(hi) : "l"(v));
}
#define FMA2(d, a, b, c) \
    asm("fma.rn.f32x2 %0, %1, %2, %3;" : "=l"(d) : "l"(a), "l"(b), "l"(c))
#define MUL2(d, a, b) \
    asm("mul.rn.f32x2 %0, %1, %2;" : "=l"(d) : "l"(a), "l"(b))
#define ADD2(d, a, b) \
    asm("add.rn.f32x2 %0, %1, %2;" : "=l"(d) : "l"(a), "l"(b))

// ---------------- monotone float->u32 encode/decode ----------------
__device__ __forceinline__ unsigned int enc_f(float c) {
    unsigned int cb = __float_as_uint(c);
    return (cb & 0x80000000u) ? ~cb : (cb | 0x80000000u);
}
__device__ __forceinline__ float dec_f(unsigned int e) {
    unsigned int cb = (e & 0x80000000u) ? (e & 0x7fffffffu) : ~e;
    return __uint_as_float(cb);
}

// ---------------- step-0 cost from raw input ----------------
__global__ void cost_kernel(const float* __restrict__ src) {
    int idx = blockIdx.x * blockDim.x + threadIdx.x;
    if (idx >= NTOT) return;
    const float4* xp = reinterpret_cast<const float4*>(src + (size_t)idx * DIM);
    float cost = 10.0f * (float)DIM;
#pragma unroll
    for (int u = 0; u < 4; ++u) {
        float4 xv = xp[u];
        float xs[4] = {xv.x, xv.y, xv.z, xv.w};
#pragma unroll
        for (int t = 0; t < 4; ++t)
            cost += xs[t] * xs[t] - 10.0f * cosf(TWOPI * xs[t]);
    }
    g_cost[idx] = cost;
}

// ---------------- rank sort: 8-way split scan + fused scatter ----------------
// grid: SPECIES * (POP/32) = 512 blocks, 256 threads.
// 32 elements per block; 8 threads per element, each scans a strided 1/8 slice.
__global__ __launch_bounds__(256) void ranksort_kernel(const float* __restrict__ src) {
    __shared__ unsigned long long skey[POP];   // 32 KB
    const int s   = blockIdx.x >> 7;                 // / (POP/32)
    const int blk = blockIdx.x & 127;
    const int eL  = blk * 32 + (threadIdx.x >> 3);   // species-local element
    const int seg = threadIdx.x & 7;

    // stage all keys for this species (coalesced LDG, conflict-free STS)
    for (int t = threadIdx.x; t < POP; t += 256) {
        unsigned int ec = enc_f(g_cost[s * POP + t]);
        skey[t] = ((unsigned long long)ec << 32) | (unsigned int)t;
    }
    __syncthreads();

    const unsigned long long kme = skey[eL];

    // scan slice: uint4 indices t*8+seg — warp reads 128 contiguous bytes/iter
    int r0 = 0, r1 = 0;
    const uint4* k4 = reinterpret_cast<const uint4*>(skey);
#pragma unroll 8
    for (int t = 0; t < (POP * 8 / 16) / 8; ++t) {   // 256 iters
        uint4 v = k4[t * 8 + seg];
        unsigned long long k0 = ((unsigned long long)v.y << 32) | v.x;
        unsigned long long k1 = ((unsigned long long)v.w << 32) | v.z;
        r0 += (int)(k0 < kme);
        r1 += (int)(k1 < kme);
    }
    int rank = r0 + r1;
    rank += __shfl_xor_sync(0xffffffffu, rank, 1);
    rank += __shfl_xor_sync(0xffffffffu, rank, 2);
    rank += __shfl_xor_sync(0xffffffffu, rank, 4);

    // fused scatter: 8 threads copy the 16-float row (2 floats each)
    int r = s * POP + rank;
    float2 xv = *reinterpret_cast<const float2*>(src + (size_t)(s * POP + eL) * DIM + 2 * seg);
    *reinterpret_cast<float2*>(g_xS + (size_t)r * DIM + 2 * seg) = xv;
    float sq = fmaf(xv.x, xv.x, xv.y * xv.y);
    sq += __shfl_xor_sync(0xffffffffu, sq, 1);
    sq += __shfl_xor_sync(0xffffffffu, sq, 2);
    sq += __shfl_xor_sync(0xffffffffu, sq, 4);
    if (seg == 0) {
        g_perm[r] = eL;
        g_scS[r] = make_float2(-LOG2E * sq, dec_f((unsigned int)(kme >> 32)));
    }
}

// ---------------- pairwise: 2 i-rows per thread, lower-triangle blocks ----------------
// grid: (POP/ISPAN, JSPLIT, SPECIES), block: 128
__global__ __launch_bounds__(128, 4) void pairwise_kernel() {
    if (blockIdx.y * JCHUNK > blockIdx.x * ISPAN + (ISPAN - 1)) return;

    __shared__ float  s_x[JCHUNK * DIM];   // 8 KB
    __shared__ float2 s_sc[JCHUNK];        // 1 KB

    const int s  = blockIdx.z;
    const int i0 = s * POP + blockIdx.x * ISPAN + threadIdx.x;
    const int i1 = i0 + 128;
    const int j0 = s * POP + blockIdx.y * JCHUNK;

    {
        const float4* src = reinterpret_cast<const float4*>(g_xS + (size_t)j0 * DIM);
        float4* dst = reinterpret_cast<float4*>(s_x);
#pragma unroll
        for (int t = threadIdx.x; t < (JCHUNK * DIM) / 4; t += 128)
            dst[t] = src[t];
        if (threadIdx.x < JCHUNK) s_sc[threadIdx.x] = g_scS[j0 + threadIdx.x];
    }
    __syncthreads();

    unsigned long long xi0[8], xi1[8];
    {
        const ulonglong2* xp0 = reinterpret_cast<const ulonglong2*>(g_xS + (size_t)i0 * DIM);
        const ulonglong2* xp1 = reinterpret_cast<const ulonglong2*>(g_xS + (size_t)i1 * DIM);
#pragma unroll
        for (int q = 0; q < 4; ++q) {
            ulonglong2 v0 = xp0[q];
            ulonglong2 v1 = xp1[q];
            xi0[2 * q] = v0.x; xi0[2 * q + 1] = v0.y;
            xi1[2 * q] = v1.x; xi1[2 * q + 1] = v1.y;
        }
    }
    const float2 sci0 = g_scS[i0];
    const float2 sci1 = g_scS[i1];
    const float ai0 = 1.0f + sci0.x, ci0 = sci0.y;
    const float ai1 = 1.0f + sci1.x, ci1 = sci1.y;

    unsigned long long acc0[8], acc1[8];
    const unsigned long long zero2 = pack2(0.0f, 0.0f);
#pragma unroll
    for (int q = 0; q < 8; ++q) { acc0[q] = zero2; acc1[q] = zero2; }
    float ws0 = 0.0f, ws1 = 0.0f;

#pragma unroll 2
    for (int jj = 0; jj < JCHUNK; ++jj) {
        const ulonglong2* xjv = reinterpret_cast<const ulonglong2*>(s_x + jj * DIM);
        ulonglong2 va = xjv[0];
        ulonglong2 vb = xjv[1];
        ulonglong2 vc = xjv[2];
        ulonglong2 vd = xjv[3];
        float2 scj = s_sc[jj];

        unsigned long long pA, pB, qA, qB;
        MUL2(pA, xi0[0], va.x);  MUL2(pB, xi0[1], va.y);
        MUL2(qA, xi1[0], va.x);  MUL2(qB, xi1[1], va.y);
        FMA2(pA, xi0[2], vb.x, pA);  FMA2(pB, xi0[3], vb.y, pB);
        FMA2(qA, xi1[2], vb.x, qA);  FMA2(qB, xi1[3], vb.y, qB);
        FMA2(pA, xi0[4], vc.x, pA);  FMA2(pB, xi0[5], vc.y, pB);
        FMA2(qA, xi1[4], vc.x, qA);  FMA2(qB, xi1[5], vc.y, qB);
        FMA2(pA, xi0[6], vd.x, pA);  FMA2(pB, xi0[7], vd.y, pB);
        FMA2(qA, xi1[6], vd.x, qA);  FMA2(qB, xi1[7], vd.y, qB);

        unsigned long long sp, sq2;
        ADD2(sp, pA, pB);
        ADD2(sq2, qA, qB);
        float p0, p1, q0, q1;
        unpack2(sp, p0, p1);
        unpack2(sq2, q0, q1);
        float d0 = p0 + p1;
        float d1 = q0 + q1;

        float t0 = fmaf(d0, 2.0f * LOG2E, ai0 + scj.x);
        float t1 = fmaf(d1, 2.0f * LOG2E, ai1 + scj.x);
        float w0, w1;
        asm("ex2.approx.f32 %0, %1;" : "=f"(w0) : "f"(t0));
        asm("ex2.approx.f32 %0, %1;" : "=f"(w1) : "f"(t1));
        w0 = (ci0 > scj.y) ? w0 : 0.0f;
        w1 = (ci1 > scj.y) ? w1 : 0.0f;

        unsigned long long w20 = pack2(w0, w0);
        unsigned long long w21 = pack2(w1, w1);
        FMA2(acc0[0], w20, va.x, acc0[0]);  FMA2(acc1[0], w21, va.x, acc1[0]);
        FMA2(acc0[1], w20, va.y, acc0[1]);  FMA2(acc1[1], w21, va.y, acc1[1]);
        FMA2(acc0[2], w20, vb.x, acc0[2]);  FMA2(acc1[2], w21, vb.x, acc1[2]);
        FMA2(acc0[3], w20, vb.y, acc0[3]);  FMA2(acc1[3], w21, vb.y, acc1[3]);
        FMA2(acc0[4], w20, vc.x, acc0[4]);  FMA2(acc1[4], w21, vc.x, acc1[4]);
        FMA2(acc0[5], w20, vc.y, acc0[5]);  FMA2(acc1[5], w21, vc.y, acc1[5]);
        FMA2(acc0[6], w20, vd.x, acc0[6]);  FMA2(acc1[6], w21, vd.x, acc1[6]);
        FMA2(acc0[7], w20, vd.y, acc0[7]);  FMA2(acc1[7], w21, vd.y, acc1[7]);
        ws0 += w0;
        ws1 += w1;
    }

    float* base = g_part + (size_t)blockIdx.y * 17 * NTOT;
#pragma unroll
    for (int q = 0; q < 8; ++q) {
        float lo, hi;
        unpack2(acc0[q], lo, hi);
        base[(2 * q) * NTOT + i0]     = lo;
        base[(2 * q + 1) * NTOT + i0] = hi;
        unpack2(acc1[q], lo, hi);
        base[(2 * q) * NTOT + i1]     = lo;
        base[(2 * q + 1) * NTOT + i1] = hi;
    }
    base[16 * NTOT + i0] = ws0;
    base[16 * NTOT + i1] = ws1;
}

// ---------------- update: 8 threads per firefly (2 dims each) ----------------
__global__ __launch_bounds__(256) void update_kernel(float* __restrict__ xout,
                                                     const float* __restrict__ noise_step,
                                                     float alpha, int do_mix) {
    int gid = blockIdx.x * 256 + threadIdx.x;   // 8*NTOT threads
    int r = gid >> 3;                            // sorted slot
    int q = gid & 7;                             // dim pair index
    int s  = r / POP;
    int rl = r % POP;
    int bi = rl / ISPAN;
    int nch = ((bi + 1) * ISPAN - 1) / JCHUNK + 1;

    int p = g_perm[r];
    int orig = s * POP + p;
    int ds = (do_mix && p >= POP / 2) ? ((s + 1) & (SPECIES - 1)) : s;
    int didx = ds * POP + p;

    float ws = 0.0f, a0 = 0.0f, a1 = 0.0f;
#pragma unroll 8
    for (int k = 0; k < nch; ++k) {
        const float* pk = g_part + (size_t)k * 17 * NTOT + r;
        ws += pk[(size_t)16 * NTOT];
        a0 += pk[(size_t)(2 * q) * NTOT];
        a1 += pk[(size_t)(2 * q + 1) * NTOT];
    }

    float2 xv = *reinterpret_cast<const float2*>(g_xS + (size_t)r * DIM + 2 * q);
    float2 nz = *reinterpret_cast<const float2*>(noise_step + (size_t)orig * DIM + 2 * q);
    const float scale = alpha * (UBV - LBV);

    float xn0 = xv.x + (a0 - ws * xv.x) + scale * (nz.x - 0.5f);
    float xn1 = xv.y + (a1 - ws * xv.y) + scale * (nz.y - 0.5f);
    xn0 = fminf(fmaxf(xn0, LBV), UBV);
    xn1 = fminf(fmaxf(xn1, LBV), UBV);
    *reinterpret_cast<float2*>(xout + (size_t)didx * DIM + 2 * q) = make_float2(xn0, xn1);

    float cost = (xn0 * xn0 - 10.0f * cosf(TWOPI * xn0))
               + (xn1 * xn1 - 10.0f * cosf(TWOPI * xn1));
#pragma unroll
    for (int m = 1; m <= 4; m <<= 1)
        cost += __shfl_xor_sync(0xffffffffu, cost, m);
    if (q == 0)
        g_cost[didx] = cost + 10.0f * (float)DIM;
}

// ---------------- launch ----------------
extern "C" void kernel_launch(void* const* d_in, const int* in_sizes, int n_in,
                              void* d_out, int out_size) {
    const float* fireflies = (const float*)d_in[0];
    const float* noise     = (const float*)d_in[1];
    float* out = (float*)d_out;

    float* xA;
    cudaGetSymbolAddress((void**)&xA, g_xA);

    dim3 pw_grid(POP / ISPAN, JSPLIT, SPECIES);
    int rs_blocks = SPECIES * (POP / 32);   // 512

    cost_kernel<<<NTOT / 256, 256>>>(fireflies);

    double alpha = 0.1;
    const float* src = fireflies;
    for (int step = 0; step < NSTEPS; ++step) {
        ranksort_kernel<<<rs_blocks, 256>>>(src);
        pairwise_kernel<<<pw_grid, 128>>>();
        float* dst = (step == NSTEPS - 1) ? out : xA;
        const float* nz = noise + (size_t)step * NTOT * DIM;
        int do_mix = (step % 25 == 0) ? 1 : 0;
        update_kernel<<<NTOT * 8 / 256, 256>>>(dst, nz, (float)alpha, do_mix);
        alpha *= 0.995;
        src = xA;
    }
}